// round 4
// baseline (speedup 1.0000x reference)
#include <cuda_runtime.h>
#include <cuda_fp16.h>
#include <cstdint>

#define DINL __device__ __forceinline__

constexpr int NROWS   = 65536;
constexpr int DFEAT   = 32;
constexpr int H       = 128;
constexpr int SPLITS  = 32;
constexpr int ROWS_PER_BLOCK = NROWS / SPLITS;   // 2048
constexpr int TILES   = ROWS_PER_BLOCK / 128;    // 16
constexpr int NTHREADS = 256;

DINL void mma16816(float* c, uint32_t a0, uint32_t a1, uint32_t a2, uint32_t a3,
                   uint32_t b0, uint32_t b1) {
    asm volatile(
        "mma.sync.aligned.m16n8k16.row.col.f32.f16.f16.f32 "
        "{%0,%1,%2,%3}, {%4,%5,%6,%7}, {%8,%9}, {%0,%1,%2,%3};"
        : "+f"(c[0]), "+f"(c[1]), "+f"(c[2]), "+f"(c[3])
        : "r"(a0), "r"(a1), "r"(a2), "r"(a3), "r"(b0), "r"(b1));
}

DINL uint32_t h2u(__half2 h) { return *reinterpret_cast<uint32_t*>(&h); }

__global__ void __launch_bounds__(NTHREADS, 1)
kan_kernel(const float* __restrict__ x,  const float* __restrict__ W1,
           const float* __restrict__ b1, const float* __restrict__ W2,
           const float* __restrict__ b2, const float* __restrict__ W3,
           const float* __restrict__ b3, float* __restrict__ out)
{
    __shared__ float w1s[H], b1s[H], b2s[H], w3s[H];
    __shared__ float part[2][4][128];

    const int tid   = threadIdx.x;
    const int d     = blockIdx.x & (DFEAT - 1);   // feature fastest -> x L2 reuse
    const int split = blockIdx.x >> 5;
    const int n0    = split * ROWS_PER_BLOCK;

    const int lane = tid & 31, warp = tid >> 5;
    const int wm = warp & 1;        // 2 row-groups of 64
    const int wn = warp >> 1;       // 4 col-groups of 32
    const int tig = lane & 3, gid = lane >> 2;

    // ---- stage small weights through SMEM ----
    for (int i = tid; i < H; i += NTHREADS) {
        w1s[i] = W1[d * H + i];
        b1s[i] = b1[d * H + i];
        b2s[i] = b2[d * H + i];
        w3s[i] = W3[d * H + i];
    }
    const float b3d = b3[d];

    // ---- B (W2) fragments in registers, once per block ----
    // mma m16n8k16 .col B frag: lane holds n = gid, k = ks*16 + 2tig{,+1,+8,+9}
    uint32_t bfrag[8][4][2];
    {
        const float* w2d = W2 + (size_t)d * H * H;
        #pragma unroll
        for (int ks = 0; ks < 8; ++ks) {
            #pragma unroll
            for (int nf = 0; nf < 4; ++nf) {
                const int n  = wn * 32 + nf * 8 + gid;
                const int ka = ks * 16 + tig * 2;
                __half2 h0 = __floats2half2_rn(w2d[(ka    ) * H + n],
                                               w2d[(ka + 1) * H + n]);
                __half2 h1v = __floats2half2_rn(w2d[(ka + 8) * H + n],
                                                w2d[(ka + 9) * H + n]);
                bfrag[ks][nf][0] = h2u(h0);
                bfrag[ks][nf][1] = h2u(h1v);
            }
        }
    }
    __syncthreads();

    // ---- per-lane packed W1/b1 for direct A-fragment construction ----
    // A frag (m16n8k16 row-major): a0=(row gid, cols c0,c0+1) a1=(row gid+8, same)
    //                              a2=(row gid, cols c0+8,c0+9) a3=(row gid+8, same)
    __half2 hw1[8][2], hb1[8][2];
    #pragma unroll
    for (int ks = 0; ks < 8; ++ks) {
        const int c0 = ks * 16 + tig * 2;
        hw1[ks][0] = __floats2half2_rn(w1s[c0],     w1s[c0 + 1]);
        hw1[ks][1] = __floats2half2_rn(w1s[c0 + 8], w1s[c0 + 9]);
        hb1[ks][0] = __floats2half2_rn(b1s[c0],     b1s[c0 + 1]);
        hb1[ks][1] = __floats2half2_rn(b1s[c0 + 8], b1s[c0 + 9]);
    }

    // epilogue constants per lane: col(nf,eb) = wn*32 + nf*8 + tig*2 + eb
    float b2r[4][2], w3r[4][2];
    #pragma unroll
    for (int nf = 0; nf < 4; ++nf) {
        #pragma unroll
        for (int eb = 0; eb < 2; ++eb) {
            const int col = wn * 32 + nf * 8 + tig * 2 + eb;
            b2r[nf][eb] = b2s[col];
            w3r[nf][eb] = w3s[col];
        }
    }

    // x rows this lane feeds: wm*64 + mf*16 + gid (+8)
    float xf[8];
    #pragma unroll
    for (int mf = 0; mf < 4; ++mf) {
        const int r = n0 + wm * 64 + mf * 16 + gid;
        xf[mf * 2 + 0] = __ldg(x + (size_t)r * DFEAT + d);
        xf[mf * 2 + 1] = __ldg(x + (size_t)(r + 8) * DFEAT + d);
    }

    const __half2 zero2 = __float2half2_rn(0.f);

    for (int t = 0; t < TILES; ++t) {
        const int buf = t & 1;

        // broadcast-half2 of x values for this tile
        uint32_t xh[8];
        #pragma unroll
        for (int i = 0; i < 8; ++i) {
            __half2 v = __half2half2(__float2half_rn(xf[i]));
            xh[i] = h2u(v);
        }

        // prefetch next tile's x (hidden under MMA phase)
        if (t + 1 < TILES) {
            #pragma unroll
            for (int mf = 0; mf < 4; ++mf) {
                const int r = n0 + (t + 1) * 128 + wm * 64 + mf * 16 + gid;
                xf[mf * 2 + 0] = __ldg(x + (size_t)r * DFEAT + d);
                xf[mf * 2 + 1] = __ldg(x + (size_t)(r + 8) * DFEAT + d);
            }
        }

        // ---- MMA: A fragments built in registers (no SMEM) ----
        float acc[4][4][4];
        #pragma unroll
        for (int mf = 0; mf < 4; ++mf)
            #pragma unroll
            for (int nf = 0; nf < 4; ++nf)
                #pragma unroll
                for (int e = 0; e < 4; ++e) acc[mf][nf][e] = 0.f;

        #pragma unroll
        for (int ks = 0; ks < 8; ++ks) {
            const __half2 w0 = hw1[ks][0], w1p = hw1[ks][1];
            const __half2 c0 = hb1[ks][0], c1p = hb1[ks][1];
            #pragma unroll
            for (int mf = 0; mf < 4; ++mf) {
                const __half2 xlo = *reinterpret_cast<const __half2*>(&xh[mf * 2]);
                const __half2 xhi = *reinterpret_cast<const __half2*>(&xh[mf * 2 + 1]);
                uint32_t a0 = h2u(__hmax2(__hfma2(xlo, w0,  c0 ), zero2));
                uint32_t a1 = h2u(__hmax2(__hfma2(xhi, w0,  c0 ), zero2));
                uint32_t a2 = h2u(__hmax2(__hfma2(xlo, w1p, c1p), zero2));
                uint32_t a3 = h2u(__hmax2(__hfma2(xhi, w1p, c1p), zero2));
                #pragma unroll
                for (int nf = 0; nf < 4; ++nf)
                    mma16816(acc[mf][nf], a0, a1, a2, a3,
                             bfrag[ks][nf][0], bfrag[ks][nf][1]);
            }
        }

        // ---- epilogue: relu(acc + b2) * W3, reduce over cols ----
        #pragma unroll
        for (int mf = 0; mf < 4; ++mf) {
            float r0 = 0.f, r1 = 0.f;
            #pragma unroll
            for (int nf = 0; nf < 4; ++nf) {
                #pragma unroll
                for (int eb = 0; eb < 2; ++eb) {
                    r0 += fmaxf(acc[mf][nf][eb]     + b2r[nf][eb], 0.f) * w3r[nf][eb];
                    r1 += fmaxf(acc[mf][nf][2 + eb] + b2r[nf][eb], 0.f) * w3r[nf][eb];
                }
            }
            r0 += __shfl_xor_sync(0xffffffffu, r0, 1);
            r0 += __shfl_xor_sync(0xffffffffu, r0, 2);
            r1 += __shfl_xor_sync(0xffffffffu, r1, 1);
            r1 += __shfl_xor_sync(0xffffffffu, r1, 2);
            if (tig == 0) {
                const int r = wm * 64 + mf * 16 + gid;
                part[buf][wn][r    ] = r0;
                part[buf][wn][r + 8] = r1;
            }
        }
        __syncthreads();

        // ---- cross-warp reduce + global accumulate ----
        if (tid < 128) {
            float s = part[buf][0][tid] + part[buf][1][tid]
                    + part[buf][2][tid] + part[buf][3][tid] + b3d;
            atomicAdd(out + n0 + t * 128 + tid, s);
        }
    }
}

extern "C" void kernel_launch(void* const* d_in, const int* in_sizes, int n_in,
                              void* d_out, int out_size) {
    const float* x  = (const float*)d_in[0];
    const float* W1 = (const float*)d_in[1];
    const float* b1 = (const float*)d_in[2];
    const float* W2 = (const float*)d_in[3];
    const float* b2 = (const float*)d_in[4];
    const float* W3 = (const float*)d_in[5];
    const float* b3 = (const float*)d_in[6];
    float* out = (float*)d_out;

    cudaMemsetAsync(d_out, 0, (size_t)out_size * sizeof(float), 0);
    kan_kernel<<<DFEAT * SPLITS, NTHREADS>>>(x, W1, b1, W2, b2, W3, b3, out);
}

// round 5
// speedup vs baseline: 1.3487x; 1.3487x over previous
#include <cuda_runtime.h>
#include <cuda_fp16.h>
#include <cstdint>

#define DINL __device__ __forceinline__

constexpr int NROWS   = 65536;
constexpr int DFEAT   = 32;
constexpr int H       = 128;
constexpr int SPLITS  = 32;
constexpr int ROWS_PER_BLOCK = NROWS / SPLITS;   // 2048
constexpr int TILES   = ROWS_PER_BLOCK / 128;    // 16
constexpr int NTHREADS = 256;

// dynamic SMEM layout (bytes)
constexpr int SM_A0   = 0;          // A tile buf0: 128 rows x 256 B (swizzled)
constexpr int SM_A1   = 32768;
constexpr int SM_W1H  = 65536;      // 64 x uint32 (half2-packed W1)
constexpr int SM_B1H  = 65792;      // 64 x uint32
constexpr int SM_B2S  = 66048;      // 128 floats
constexpr int SM_W3S  = 66560;      // 128 floats
constexpr int SM_TOTAL = 67072;

DINL uint32_t smem_u32(const void* p) {
    uint32_t a;
    asm("{ .reg .u64 t; cvta.to.shared.u64 t, %1; cvt.u32.u64 %0, t; }"
        : "=r"(a) : "l"(p));
    return a;
}

DINL void ldsm_x4(uint32_t& a0, uint32_t& a1, uint32_t& a2, uint32_t& a3,
                  uint32_t addr) {
    asm volatile("ldmatrix.sync.aligned.m8n8.x4.shared.b16 {%0,%1,%2,%3}, [%4];"
                 : "=r"(a0), "=r"(a1), "=r"(a2), "=r"(a3) : "r"(addr));
}

DINL void mma16816(float* c, uint32_t a0, uint32_t a1, uint32_t a2, uint32_t a3,
                   uint32_t b0, uint32_t b1) {
    asm volatile(
        "mma.sync.aligned.m16n8k16.row.col.f32.f16.f16.f32 "
        "{%0,%1,%2,%3}, {%4,%5,%6,%7}, {%8,%9}, {%0,%1,%2,%3};"
        : "+f"(c[0]), "+f"(c[1]), "+f"(c[2]), "+f"(c[3])
        : "r"(a0), "r"(a1), "r"(a2), "r"(a3), "r"(b0), "r"(b1));
}

DINL uint32_t h2u(__half2 h) { return *reinterpret_cast<uint32_t*>(&h); }
DINL __half2 u2h(uint32_t u) { return *reinterpret_cast<__half2*>(&u); }

__global__ void __launch_bounds__(NTHREADS, 1)
kan_kernel(const float* __restrict__ x,  const float* __restrict__ W1,
           const float* __restrict__ b1, const float* __restrict__ W2,
           const float* __restrict__ b2, const float* __restrict__ W3,
           const float* __restrict__ b3, float* __restrict__ out)
{
    extern __shared__ char smem[];
    const uint32_t sb = smem_u32(smem);

    uint32_t* w1h = reinterpret_cast<uint32_t*>(smem + SM_W1H);
    uint32_t* b1h = reinterpret_cast<uint32_t*>(smem + SM_B1H);
    float*    b2s = reinterpret_cast<float*>(smem + SM_B2S);
    float*    w3s = reinterpret_cast<float*>(smem + SM_W3S);

    const int tid   = threadIdx.x;
    const int d     = blockIdx.x & (DFEAT - 1);   // feature fastest -> x L2 reuse
    const int split = blockIdx.x >> 5;
    const int n0    = split * ROWS_PER_BLOCK;

    const int lane = tid & 31, warp = tid >> 5;
    const int wm = warp & 1;        // 2 row-groups of 64
    const int wn = warp >> 1;       // 4 col-groups of 32
    const int tig = lane & 3, gid = lane >> 2;

    // ---- prologue: pack W1/b1 as half2 into SMEM; stage b2/W3 ----
    for (int i = tid; i < 64; i += NTHREADS) {
        w1h[i] = h2u(__floats2half2_rn(W1[d * H + 2 * i], W1[d * H + 2 * i + 1]));
        b1h[i] = h2u(__floats2half2_rn(b1[d * H + 2 * i], b1[d * H + 2 * i + 1]));
    }
    for (int i = tid; i < H; i += NTHREADS) {
        b2s[i] = b2[d * H + i];
        w3s[i] = W3[d * H + i];
    }
    const float b3d = b3[d];

    // ---- B (W2) fragments in registers, once per block ----
    uint32_t bfrag[8][4][2];
    {
        const float* w2d = W2 + (size_t)d * H * H;
        #pragma unroll
        for (int ks = 0; ks < 8; ++ks) {
            #pragma unroll
            for (int nf = 0; nf < 4; ++nf) {
                const int n  = wn * 32 + nf * 8 + gid;
                const int ka = ks * 16 + tig * 2;
                bfrag[ks][nf][0] = h2u(__floats2half2_rn(w2d[(ka    ) * H + n],
                                                         w2d[(ka + 1) * H + n]));
                bfrag[ks][nf][1] = h2u(__floats2half2_rn(w2d[(ka + 8) * H + n],
                                                         w2d[(ka + 9) * H + n]));
            }
        }
    }
    __syncthreads();   // weights visible before any produce

    const int prow  = tid >> 1;      // producer row (2 threads/row)
    const int phalf = tid & 1;
    const __half2 zero2 = __float2half2_rn(0.f);

    // produce one 8-col granule g of row prow into buffer A (half2 math)
    auto produce_granule = [&](char* A, uint32_t xh, int g) {
        const uint4 wv = *reinterpret_cast<const uint4*>(w1h + g * 4);
        const uint4 bv = *reinterpret_cast<const uint4*>(b1h + g * 4);
        const __half2 x2 = u2h(xh);
        uint4 u;
        u.x = h2u(__hmax2(__hfma2(x2, u2h(wv.x), u2h(bv.x)), zero2));
        u.y = h2u(__hmax2(__hfma2(x2, u2h(wv.y), u2h(bv.y)), zero2));
        u.z = h2u(__hmax2(__hfma2(x2, u2h(wv.z), u2h(bv.z)), zero2));
        u.w = h2u(__hmax2(__hfma2(x2, u2h(wv.w), u2h(bv.w)), zero2));
        const uint32_t byte = (uint32_t)prow * 256u
                            + (uint32_t)((g ^ (prow & 15)) << 4);
        *reinterpret_cast<uint4*>(A + byte) = u;
    };

    // produce tile 0
    {
        const float xv = x[(size_t)(n0 + prow) * DFEAT + d];
        const uint32_t xh = h2u(__half2half2(__float2half_rn(xv)));
        #pragma unroll
        for (int j = 0; j < 8; ++j)
            produce_granule(smem + SM_A0, xh, phalf * 8 + j);
    }
    __syncthreads();

    // epilogue constants per lane: col(nf,eb) = wn*32 + nf*8 + tig*2 + eb
    float b2r[4][2], w3r[4][2];
    #pragma unroll
    for (int nf = 0; nf < 4; ++nf) {
        #pragma unroll
        for (int eb = 0; eb < 2; ++eb) {
            const int col = wn * 32 + nf * 8 + tig * 2 + eb;
            b2r[nf][eb] = b2s[col];
            w3r[nf][eb] = w3s[col];
        }
    }

    // ldmatrix lane-address components
    const int g2 = lane >> 3;
    const int ri = lane & 7;
    const int row_local = (g2 & 1) * 8 + ri;
    const int gran_hi   = g2 >> 1;

    for (int t = 0; t < TILES; ++t) {
        const int buf = t & 1;
        const uint32_t Abase = sb + (buf ? SM_A1 : SM_A0);
        char* Anext = smem + (buf ? SM_A0 : SM_A1);

        // prefetch next tile's x (consumed at ks>=4, ~half the MMA phase later)
        float xnf = 0.f;
        const bool have_next = (t + 1 < TILES);
        if (have_next)
            xnf = x[(size_t)(n0 + (t + 1) * 128 + prow) * DFEAT + d];

        float acc[4][4][4];
        #pragma unroll
        for (int mf = 0; mf < 4; ++mf)
            #pragma unroll
            for (int nf = 0; nf < 4; ++nf)
                #pragma unroll
                for (int e = 0; e < 4; ++e) acc[mf][nf][e] = 0.f;

        uint32_t xh_next = 0;

        #pragma unroll
        for (int ks = 0; ks < 8; ++ks) {
            #pragma unroll
            for (int mf = 0; mf < 4; ++mf) {
                const int rowfull = wm * 64 + mf * 16 + row_local;
                const int gran    = ks * 2 + gran_hi;
                const uint32_t addr = Abase + (uint32_t)rowfull * 256u
                                    + (uint32_t)((gran ^ (rowfull & 15)) << 4);
                uint32_t a0, a1, a2, a3;
                ldsm_x4(a0, a1, a2, a3, addr);
                #pragma unroll
                for (int nf = 0; nf < 4; ++nf)
                    mma16816(acc[mf][nf], a0, a1, a2, a3,
                             bfrag[ks][nf][0], bfrag[ks][nf][1]);
            }
            // interleaved produce of next tile: 2 granules per ks, ks>=4
            if (ks >= 4 && have_next) {
                if (ks == 4)
                    xh_next = h2u(__half2half2(__float2half_rn(xnf)));
                const int j = (ks - 4) * 2;
                produce_granule(Anext, xh_next, phalf * 8 + j);
                produce_granule(Anext, xh_next, phalf * 8 + j + 1);
            }
        }

        // ---- epilogue: relu(acc + b2) * W3, shfl-reduce, direct atomicAdd ----
        #pragma unroll
        for (int mf = 0; mf < 4; ++mf) {
            float r0 = 0.f, r1 = 0.f;
            #pragma unroll
            for (int nf = 0; nf < 4; ++nf) {
                #pragma unroll
                for (int eb = 0; eb < 2; ++eb) {
                    r0 += fmaxf(acc[mf][nf][eb]     + b2r[nf][eb], 0.f) * w3r[nf][eb];
                    r1 += fmaxf(acc[mf][nf][2 + eb] + b2r[nf][eb], 0.f) * w3r[nf][eb];
                }
            }
            r0 += __shfl_xor_sync(0xffffffffu, r0, 1);
            r0 += __shfl_xor_sync(0xffffffffu, r0, 2);
            r1 += __shfl_xor_sync(0xffffffffu, r1, 1);
            r1 += __shfl_xor_sync(0xffffffffu, r1, 2);
            if (tig == 0) {
                const int r = n0 + t * 128 + wm * 64 + mf * 16 + gid;
                const float bias = (wn == 0) ? b3d : 0.f;
                atomicAdd(out + r,     r0 + bias);
                atomicAdd(out + r + 8, r1 + bias);
            }
        }

        __syncthreads();   // A-buffer handoff (produce(t+1) complete for all)
    }
}

extern "C" void kernel_launch(void* const* d_in, const int* in_sizes, int n_in,
                              void* d_out, int out_size) {
    const float* x  = (const float*)d_in[0];
    const float* W1 = (const float*)d_in[1];
    const float* b1 = (const float*)d_in[2];
    const float* W2 = (const float*)d_in[3];
    const float* b2 = (const float*)d_in[4];
    const float* W3 = (const float*)d_in[5];
    const float* b3 = (const float*)d_in[6];
    float* out = (float*)d_out;

    cudaFuncSetAttribute(kan_kernel, cudaFuncAttributeMaxDynamicSharedMemorySize,
                         SM_TOTAL);
    cudaMemsetAsync(d_out, 0, (size_t)out_size * sizeof(float), 0);
    kan_kernel<<<DFEAT * SPLITS, NTHREADS, SM_TOTAL>>>(x, W1, b1, W2, b2, W3, b3, out);
}